// round 15
// baseline (speedup 1.0000x reference)
#include <cuda_runtime.h>

// Fixed problem shape (from reference): N=50000, E=800000, IN=128, HID=32, HEADS=4
#define NMAX 50000
#define EMAX 800000
#define NEG_SLOPE 0.2f
#define SCAN_BLK 256

// -------- scratch (device globals: allocation-free, graph-capturable) --------
__device__ float g_h1 [NMAX * 128];    // layer1 raw features
__device__ float g_x2 [NMAX * 128];    // elu(layer1 out) = layer2 input
__device__ float g_als1[NMAX * 4];
__device__ float g_ald1[NMAX * 4];
__device__ float g_h2 [NMAX * 32];
__device__ float g_als2[NMAX];
__device__ float g_ald2[NMAX];
// CSR by destination
__device__ int g_cnt [NMAX];
__device__ int g_row [NMAX + 1];
__device__ int g_wpos[NMAX];
__device__ int g_csr [EMAX];
__device__ int g_bsum[512];

__device__ __forceinline__ float leaky(float v) {
    return v > 0.0f ? v : NEG_SLOPE * v;
}

// -------- CSR build --------
__global__ void k_zero(int n) {
    int i = blockIdx.x * blockDim.x + threadIdx.x;
    if (i < n) g_cnt[i] = 0;
}

__global__ void k_count(const int* __restrict__ ei, int e) {
    int t = blockIdx.x * blockDim.x + threadIdx.x;
    if (t < e) atomicAdd(&g_cnt[ei[e + t]], 1);   // dst
}

__global__ void k_bsum(int n) {
    __shared__ int sh[8];
    int i = blockIdx.x * SCAN_BLK + threadIdx.x;
    int c = (i < n) ? g_cnt[i] : 0;
#pragma unroll
    for (int o = 16; o > 0; o >>= 1) c += __shfl_xor_sync(0xffffffffu, c, o);
    if ((threadIdx.x & 31) == 0) sh[threadIdx.x >> 5] = c;
    __syncthreads();
    if (threadIdx.x == 0) {
        int v = 0;
#pragma unroll
        for (int w = 0; w < 8; w++) v += sh[w];
        g_bsum[blockIdx.x] = v;
    }
}

__global__ void k_bscan(int nblk) {
    __shared__ int sh[SCAN_BLK];
    int tid = threadIdx.x;
    int v = (tid < nblk) ? g_bsum[tid] : 0;
    sh[tid] = v;
    __syncthreads();
    for (int d = 1; d < SCAN_BLK; d <<= 1) {
        int t = (tid >= d) ? sh[tid - d] : 0;
        __syncthreads();
        sh[tid] += t;
        __syncthreads();
    }
    if (tid < nblk) g_bsum[tid] = sh[tid] - v;   // exclusive
}

__global__ void k_rowfill(int n) {
    __shared__ int sh[SCAN_BLK];
    int tid = threadIdx.x;
    int i = blockIdx.x * SCAN_BLK + tid;
    int c = (i < n) ? g_cnt[i] : 0;
    sh[tid] = c;
    __syncthreads();
    for (int d = 1; d < SCAN_BLK; d <<= 1) {
        int t = (tid >= d) ? sh[tid - d] : 0;
        __syncthreads();
        sh[tid] += t;
        __syncthreads();
    }
    int pref = g_bsum[blockIdx.x] + sh[tid] - c;   // exclusive prefix
    if (i < n) {
        g_row[i] = pref;
        g_wpos[i] = pref;
        if (i == n - 1) g_row[n] = pref + c;
    }
}

__global__ void k_fill(const int* __restrict__ ei, int e) {
    int t = blockIdx.x * blockDim.x + threadIdx.x;
    if (t >= e) return;
    int s = ei[t], d = ei[e + t];
    int pos = atomicAdd(&g_wpos[d], 1);
    g_csr[pos] = s;
}

// -------- layer1 GEMM (x @ W1) fused with logits; FOUR nodes per warp --------
// lane owns output cols 4*lane..4*lane+3 (head = lane/8); W1 load amortized x4
__global__ void k_gemm1(int n, const float* __restrict__ x, const float* __restrict__ W1,
                        const float* __restrict__ as1, const float* __restrict__ ad1) {
    int gw   = (blockIdx.x * blockDim.x + threadIdx.x) >> 5;
    int lane = threadIdx.x & 31;
    int n0 = gw * 4;
    if (n0 >= n) return;

    float xv[4][4];
#pragma unroll
    for (int j = 0; j < 4; j++) {
        bool ok = (n0 + j < n);
#pragma unroll
        for (int r = 0; r < 4; r++)
            xv[j][r] = ok ? x[(n0 + j) * 128 + lane + 32 * r] : 0.0f;
    }

    float acc[4][4];
#pragma unroll
    for (int j = 0; j < 4; j++)
#pragma unroll
        for (int q = 0; q < 4; q++) acc[j][q] = 0.0f;

#pragma unroll
    for (int k = 0; k < 128; k++) {
        float4 wv = *(const float4*)&W1[k * 128 + 4 * lane];   // L1-resident (64KB)
#pragma unroll
        for (int j = 0; j < 4; j++) {
            float xk = __shfl_sync(0xffffffffu, xv[j][k >> 5], k & 31);
            acc[j][0] += xk * wv.x; acc[j][1] += xk * wv.y;
            acc[j][2] += xk * wv.z; acc[j][3] += xk * wv.w;
        }
    }

    float4 sa = *(const float4*)&as1[4 * lane];
    float4 da = *(const float4*)&ad1[4 * lane];

#pragma unroll
    for (int j = 0; j < 4; j++) {
        if (n0 + j >= n) break;
        *(float4*)&g_h1[(n0 + j) * 128 + 4 * lane] =
            make_float4(acc[j][0], acc[j][1], acc[j][2], acc[j][3]);
        float ps = acc[j][0] * sa.x + acc[j][1] * sa.y + acc[j][2] * sa.z + acc[j][3] * sa.w;
        float pd = acc[j][0] * da.x + acc[j][1] * da.y + acc[j][2] * da.z + acc[j][3] * da.w;
#pragma unroll
        for (int o = 1; o < 8; o <<= 1) {
            ps += __shfl_xor_sync(0xffffffffu, ps, o);
            pd += __shfl_xor_sync(0xffffffffu, pd, o);
        }
        if ((lane & 7) == 0) {
            int h = lane >> 3;
            g_als1[(n0 + j) * 4 + h] = ps;
            g_ald1[(n0 + j) * 4 + h] = pd;
        }
    }
}

// -------- layer1 aggregation: warp per dst node, single-pass (no segment max) --------
// exp(e)/sum(exp(e)) == exp(e-max)/sum(exp(e-max)); logits are O(10) so fp32 is safe.
__global__ void k_agg1(int n, const float* __restrict__ b1) {
    int node = (blockIdx.x * blockDim.x + threadIdx.x) >> 5;
    int lane = threadIdx.x & 31;
    if (node >= n) return;
    int beg = g_row[node], end = g_row[node + 1];

    int head = lane >> 3;
    float dlh = g_ald1[node * 4 + head];

    float den = 0.f, a0 = 0.f, a1 = 0.f, a2 = 0.f, a3 = 0.f;
    { // self loop
        float slh = g_als1[node * 4 + head];
        float w = __expf(leaky(slh + dlh));
        den += w;
        float4 hv = *(const float4*)&g_h1[node * 128 + 4 * lane];
        a0 += w * hv.x; a1 += w * hv.y; a2 += w * hv.z; a3 += w * hv.w;
    }
#pragma unroll 2
    for (int i = beg; i < end; i++) {
        int s = g_csr[i];                        // uniform across warp
        float slh = g_als1[s * 4 + head];        // broadcast within head
        float w = __expf(leaky(slh + dlh));
        den += w;
        float4 hv = *(const float4*)&g_h1[s * 128 + 4 * lane];
        a0 += w * hv.x; a1 += w * hv.y; a2 += w * hv.z; a3 += w * hv.w;
    }
    float inv = 1.0f / (den + 1e-16f);
    float4 bb = *(const float4*)&b1[4 * lane];
    float v0 = a0 * inv + bb.x, v1 = a1 * inv + bb.y;
    float v2 = a2 * inv + bb.z, v3 = a3 * inv + bb.w;
    v0 = v0 > 0.f ? v0 : (__expf(v0) - 1.0f);
    v1 = v1 > 0.f ? v1 : (__expf(v1) - 1.0f);
    v2 = v2 > 0.f ? v2 : (__expf(v2) - 1.0f);
    v3 = v3 > 0.f ? v3 : (__expf(v3) - 1.0f);
    *(float4*)&g_x2[node * 128 + 4 * lane] = make_float4(v0, v1, v2, v3);
}

// -------- layer2 GEMM (x2 @ W2) fused with logits; FOUR nodes per warp, lane = col --------
__global__ void k_gemm2(int n, const float* __restrict__ W2,
                        const float* __restrict__ as2, const float* __restrict__ ad2) {
    int gw   = (blockIdx.x * blockDim.x + threadIdx.x) >> 5;
    int lane = threadIdx.x & 31;
    int n0 = gw * 4;
    if (n0 >= n) return;

    float xv[4][4];
#pragma unroll
    for (int j = 0; j < 4; j++) {
        bool ok = (n0 + j < n);
#pragma unroll
        for (int r = 0; r < 4; r++)
            xv[j][r] = ok ? g_x2[(n0 + j) * 128 + lane + 32 * r] : 0.0f;
    }

    float acc[4] = {0.f, 0.f, 0.f, 0.f};
#pragma unroll
    for (int k = 0; k < 128; k++) {
        float wk = W2[k * 32 + lane];            // L1-resident (16KB)
#pragma unroll
        for (int j = 0; j < 4; j++) {
            float xk = __shfl_sync(0xffffffffu, xv[j][k >> 5], k & 31);
            acc[j] += xk * wk;
        }
    }

    float s2 = as2[lane], d2 = ad2[lane];
#pragma unroll
    for (int j = 0; j < 4; j++) {
        if (n0 + j >= n) break;
        g_h2[(n0 + j) * 32 + lane] = acc[j];
        float ps = acc[j] * s2, pd = acc[j] * d2;
#pragma unroll
        for (int o = 16; o > 0; o >>= 1) {
            ps += __shfl_xor_sync(0xffffffffu, ps, o);
            pd += __shfl_xor_sync(0xffffffffu, pd, o);
        }
        if (lane == 0) { g_als2[n0 + j] = ps; g_ald2[n0 + j] = pd; }
    }
}

// -------- layer2 aggregation: single-pass, warp per dst node, lane = col --------
__global__ void k_agg2(int n, const float* __restrict__ b2, float* __restrict__ out) {
    int node = (blockIdx.x * blockDim.x + threadIdx.x) >> 5;
    int lane = threadIdx.x & 31;
    if (node >= n) return;
    int beg = g_row[node], end = g_row[node + 1];

    float dld = g_ald2[node];

    float den = 0.f, acc = 0.f;
    { // self loop
        float w = __expf(leaky(g_als2[node] + dld));
        den += w;
        acc += w * g_h2[node * 32 + lane];
    }
#pragma unroll 2
    for (int i = beg; i < end; i++) {
        int s = g_csr[i];
        float w = __expf(leaky(g_als2[s] + dld));
        den += w;
        acc += w * g_h2[s * 32 + lane];
    }
    out[node * 32 + lane] = acc / (den + 1e-16f) + b2[lane];
}

extern "C" void kernel_launch(void* const* d_in, const int* in_sizes, int n_in,
                              void* d_out, int out_size) {
    const float* x   = (const float*)d_in[0];
    const int*   ei  = (const int*)d_in[1];     // int64 inputs delivered as int32
    const float* W1  = (const float*)d_in[2];
    const float* as1 = (const float*)d_in[3];
    const float* ad1 = (const float*)d_in[4];
    const float* b1  = (const float*)d_in[5];
    const float* W2  = (const float*)d_in[6];
    const float* as2 = (const float*)d_in[7];
    const float* ad2 = (const float*)d_in[8];
    const float* b2  = (const float*)d_in[9];
    float* out = (float*)d_out;

    int n = in_sizes[0] / 128;   // 50000
    int e = in_sizes[1] / 2;     // 800000
    int nblk = (n + SCAN_BLK - 1) / SCAN_BLK;   // 196 <= 256
    int nquad = (n + 3) / 4;

    // CSR build
    k_zero   <<<(n + 255) / 256, 256>>>(n);
    k_count  <<<(e + 255) / 256, 256>>>(ei, e);
    k_bsum   <<<nblk, SCAN_BLK>>>(n);
    k_bscan  <<<1, SCAN_BLK>>>(nblk);
    k_rowfill<<<nblk, SCAN_BLK>>>(n);
    k_fill   <<<(e + 255) / 256, 256>>>(ei, e);
    // layer 1
    k_gemm1<<<(nquad + 7) / 8, 256>>>(n, x, W1, as1, ad1);
    k_agg1 <<<(n + 7) / 8, 256>>>(n, b1);
    // layer 2
    k_gemm2<<<(nquad + 7) / 8, 256>>>(n, W2, as2, ad2);
    k_agg2 <<<(n + 7) / 8, 256>>>(n, b2, out);
}

// round 16
// speedup vs baseline: 1.3155x; 1.3155x over previous
#include <cuda_runtime.h>

// Fixed problem shape (from reference): N=50000, E=800000, IN=128, HID=32, HEADS=4
#define NMAX 50000
#define EMAX 800000
#define NEG_SLOPE 0.2f
#define SCAN_BLK 256

// -------- scratch (device globals: allocation-free, graph-capturable) --------
__device__ float g_h1 [NMAX * 128];    // layer1 raw features
__device__ float g_x2 [NMAX * 128];    // elu(layer1 out) = layer2 input
__device__ float g_als1[NMAX * 4];
__device__ float g_ald1[NMAX * 4];
__device__ float g_h2 [NMAX * 32];
__device__ float g_als2[NMAX];
__device__ float g_ald2[NMAX];
// CSR by destination
__device__ int g_cnt [NMAX];
__device__ int g_row [NMAX + 1];
__device__ int g_wpos[NMAX];
__device__ int g_csr [EMAX];
__device__ int g_bsum[512];

__device__ __forceinline__ float leaky(float v) {
    return v > 0.0f ? v : NEG_SLOPE * v;
}

// -------- CSR build --------
__global__ void k_zero(int n) {
    int i = blockIdx.x * blockDim.x + threadIdx.x;
    if (i < n) g_cnt[i] = 0;
}

__global__ void k_count(const int* __restrict__ ei, int e) {
    int t = blockIdx.x * blockDim.x + threadIdx.x;
    if (t < e) atomicAdd(&g_cnt[ei[e + t]], 1);   // dst
}

__global__ void k_bsum(int n) {
    __shared__ int sh[8];
    int i = blockIdx.x * SCAN_BLK + threadIdx.x;
    int c = (i < n) ? g_cnt[i] : 0;
#pragma unroll
    for (int o = 16; o > 0; o >>= 1) c += __shfl_xor_sync(0xffffffffu, c, o);
    if ((threadIdx.x & 31) == 0) sh[threadIdx.x >> 5] = c;
    __syncthreads();
    if (threadIdx.x == 0) {
        int v = 0;
#pragma unroll
        for (int w = 0; w < 8; w++) v += sh[w];
        g_bsum[blockIdx.x] = v;
    }
}

__global__ void k_bscan(int nblk) {
    __shared__ int sh[SCAN_BLK];
    int tid = threadIdx.x;
    int v = (tid < nblk) ? g_bsum[tid] : 0;
    sh[tid] = v;
    __syncthreads();
    for (int d = 1; d < SCAN_BLK; d <<= 1) {
        int t = (tid >= d) ? sh[tid - d] : 0;
        __syncthreads();
        sh[tid] += t;
        __syncthreads();
    }
    if (tid < nblk) g_bsum[tid] = sh[tid] - v;   // exclusive
}

__global__ void k_rowfill(int n) {
    __shared__ int sh[SCAN_BLK];
    int tid = threadIdx.x;
    int i = blockIdx.x * SCAN_BLK + tid;
    int c = (i < n) ? g_cnt[i] : 0;
    sh[tid] = c;
    __syncthreads();
    for (int d = 1; d < SCAN_BLK; d <<= 1) {
        int t = (tid >= d) ? sh[tid - d] : 0;
        __syncthreads();
        sh[tid] += t;
        __syncthreads();
    }
    int pref = g_bsum[blockIdx.x] + sh[tid] - c;   // exclusive prefix
    if (i < n) {
        g_row[i] = pref;
        g_wpos[i] = pref;
        if (i == n - 1) g_row[n] = pref + c;
    }
}

__global__ void k_fill(const int* __restrict__ ei, int e) {
    int t = blockIdx.x * blockDim.x + threadIdx.x;
    if (t >= e) return;
    int s = ei[t], d = ei[e + t];
    int pos = atomicAdd(&g_wpos[d], 1);
    g_csr[pos] = s;
}

// -------- layer1 GEMM (x @ W1) fused with logits; TWO nodes per warp --------
// lane owns output cols 4*lane..4*lane+3 (head = lane/8); W1 load amortized x2
__global__ void k_gemm1(int n, const float* __restrict__ x, const float* __restrict__ W1,
                        const float* __restrict__ as1, const float* __restrict__ ad1) {
    int gw   = (blockIdx.x * blockDim.x + threadIdx.x) >> 5;
    int lane = threadIdx.x & 31;
    int n0 = gw * 2;
    if (n0 >= n) return;
    bool has2 = (n0 + 1 < n);

    float xv0[4], xv1[4];
#pragma unroll
    for (int r = 0; r < 4; r++) {
        xv0[r] = x[n0 * 128 + lane + 32 * r];
        xv1[r] = has2 ? x[(n0 + 1) * 128 + lane + 32 * r] : 0.0f;
    }

    float b00 = 0.f, b01 = 0.f, b02 = 0.f, b03 = 0.f;
    float b10 = 0.f, b11 = 0.f, b12 = 0.f, b13 = 0.f;
#pragma unroll
    for (int k = 0; k < 128; k++) {
        float xk0 = __shfl_sync(0xffffffffu, xv0[k >> 5], k & 31);
        float xk1 = __shfl_sync(0xffffffffu, xv1[k >> 5], k & 31);
        float4 wv = *(const float4*)&W1[k * 128 + 4 * lane];   // L1-resident (64KB)
        b00 += xk0 * wv.x; b01 += xk0 * wv.y; b02 += xk0 * wv.z; b03 += xk0 * wv.w;
        b10 += xk1 * wv.x; b11 += xk1 * wv.y; b12 += xk1 * wv.z; b13 += xk1 * wv.w;
    }

    float4 sa = *(const float4*)&as1[4 * lane];
    float4 da = *(const float4*)&ad1[4 * lane];

    // node n0
    *(float4*)&g_h1[n0 * 128 + 4 * lane] = make_float4(b00, b01, b02, b03);
    float ps0 = b00 * sa.x + b01 * sa.y + b02 * sa.z + b03 * sa.w;
    float pd0 = b00 * da.x + b01 * da.y + b02 * da.z + b03 * da.w;
    float ps1 = b10 * sa.x + b11 * sa.y + b12 * sa.z + b13 * sa.w;
    float pd1 = b10 * da.x + b11 * da.y + b12 * da.z + b13 * da.w;
#pragma unroll
    for (int o = 1; o < 8; o <<= 1) {
        ps0 += __shfl_xor_sync(0xffffffffu, ps0, o);
        pd0 += __shfl_xor_sync(0xffffffffu, pd0, o);
        ps1 += __shfl_xor_sync(0xffffffffu, ps1, o);
        pd1 += __shfl_xor_sync(0xffffffffu, pd1, o);
    }
    if ((lane & 7) == 0) {
        int h = lane >> 3;
        g_als1[n0 * 4 + h] = ps0;
        g_ald1[n0 * 4 + h] = pd0;
    }
    if (has2) {
        *(float4*)&g_h1[(n0 + 1) * 128 + 4 * lane] = make_float4(b10, b11, b12, b13);
        if ((lane & 7) == 0) {
            int h = lane >> 3;
            g_als1[(n0 + 1) * 4 + h] = ps1;
            g_ald1[(n0 + 1) * 4 + h] = pd1;
        }
    }
}

// -------- layer1 aggregation: warp per dst node, single-pass, edge-paired (MLP=2) ----
__global__ void k_agg1(int n, const float* __restrict__ b1) {
    int node = (blockIdx.x * blockDim.x + threadIdx.x) >> 5;
    int lane = threadIdx.x & 31;
    if (node >= n) return;
    int beg = g_row[node], end = g_row[node + 1];

    int head = lane >> 3;
    float dlh = g_ald1[node * 4 + head];

    float den = 0.f, a0 = 0.f, a1 = 0.f, a2 = 0.f, a3 = 0.f;
    { // self loop
        float slh = g_als1[node * 4 + head];
        float w = __expf(leaky(slh + dlh));
        den += w;
        float4 hv = *(const float4*)&g_h1[node * 128 + 4 * lane];
        a0 += w * hv.x; a1 += w * hv.y; a2 += w * hv.z; a3 += w * hv.w;
    }
    int i = beg;
    for (; i + 2 <= end; i += 2) {
        // issue both edges' loads before any consumption (MLP=2)
        int s0 = g_csr[i], s1 = g_csr[i + 1];
        float sl0 = g_als1[s0 * 4 + head];
        float sl1 = g_als1[s1 * 4 + head];
        float4 h0 = *(const float4*)&g_h1[s0 * 128 + 4 * lane];
        float4 h1 = *(const float4*)&g_h1[s1 * 128 + 4 * lane];
        float w0 = __expf(leaky(sl0 + dlh));
        float w1 = __expf(leaky(sl1 + dlh));
        den += w0 + w1;
        a0 += w0 * h0.x + w1 * h1.x;
        a1 += w0 * h0.y + w1 * h1.y;
        a2 += w0 * h0.z + w1 * h1.z;
        a3 += w0 * h0.w + w1 * h1.w;
    }
    if (i < end) {
        int s = g_csr[i];
        float slh = g_als1[s * 4 + head];
        float w = __expf(leaky(slh + dlh));
        den += w;
        float4 hv = *(const float4*)&g_h1[s * 128 + 4 * lane];
        a0 += w * hv.x; a1 += w * hv.y; a2 += w * hv.z; a3 += w * hv.w;
    }
    float inv = 1.0f / (den + 1e-16f);
    float4 bb = *(const float4*)&b1[4 * lane];
    float v0 = a0 * inv + bb.x, v1 = a1 * inv + bb.y;
    float v2 = a2 * inv + bb.z, v3 = a3 * inv + bb.w;
    v0 = v0 > 0.f ? v0 : (__expf(v0) - 1.0f);
    v1 = v1 > 0.f ? v1 : (__expf(v1) - 1.0f);
    v2 = v2 > 0.f ? v2 : (__expf(v2) - 1.0f);
    v3 = v3 > 0.f ? v3 : (__expf(v3) - 1.0f);
    *(float4*)&g_x2[node * 128 + 4 * lane] = make_float4(v0, v1, v2, v3);
}

// -------- layer2 GEMM (x2 @ W2) fused with logits; TWO nodes per warp, lane = col --------
__global__ void k_gemm2(int n, const float* __restrict__ W2,
                        const float* __restrict__ as2, const float* __restrict__ ad2) {
    int gw   = (blockIdx.x * blockDim.x + threadIdx.x) >> 5;
    int lane = threadIdx.x & 31;
    int n0 = gw * 2;
    if (n0 >= n) return;
    bool has2 = (n0 + 1 < n);

    float xv0[4], xv1[4];
#pragma unroll
    for (int r = 0; r < 4; r++) {
        xv0[r] = g_x2[n0 * 128 + lane + 32 * r];
        xv1[r] = has2 ? g_x2[(n0 + 1) * 128 + lane + 32 * r] : 0.0f;
    }

    float acc0 = 0.0f, acc1 = 0.0f;
#pragma unroll
    for (int k = 0; k < 128; k++) {
        float xk0 = __shfl_sync(0xffffffffu, xv0[k >> 5], k & 31);
        float xk1 = __shfl_sync(0xffffffffu, xv1[k >> 5], k & 31);
        float wk = W2[k * 32 + lane];            // L1-resident (16KB)
        acc0 += xk0 * wk;
        acc1 += xk1 * wk;
    }
    g_h2[n0 * 32 + lane] = acc0;
    if (has2) g_h2[(n0 + 1) * 32 + lane] = acc1;

    float s2 = as2[lane], d2 = ad2[lane];
    float ps0 = acc0 * s2, pd0 = acc0 * d2;
    float ps1 = acc1 * s2, pd1 = acc1 * d2;
#pragma unroll
    for (int o = 16; o > 0; o >>= 1) {
        ps0 += __shfl_xor_sync(0xffffffffu, ps0, o);
        pd0 += __shfl_xor_sync(0xffffffffu, pd0, o);
        ps1 += __shfl_xor_sync(0xffffffffu, ps1, o);
        pd1 += __shfl_xor_sync(0xffffffffu, pd1, o);
    }
    if (lane == 0) {
        g_als2[n0] = ps0; g_ald2[n0] = pd0;
        if (has2) { g_als2[n0 + 1] = ps1; g_ald2[n0 + 1] = pd1; }
    }
}

// -------- layer2 aggregation: single-pass, edge-paired, warp per dst node --------
__global__ void k_agg2(int n, const float* __restrict__ b2, float* __restrict__ out) {
    int node = (blockIdx.x * blockDim.x + threadIdx.x) >> 5;
    int lane = threadIdx.x & 31;
    if (node >= n) return;
    int beg = g_row[node], end = g_row[node + 1];

    float dld = g_ald2[node];

    float den = 0.f, acc = 0.f;
    { // self loop
        float w = __expf(leaky(g_als2[node] + dld));
        den += w;
        acc += w * g_h2[node * 32 + lane];
    }
    int i = beg;
    for (; i + 2 <= end; i += 2) {
        int s0 = g_csr[i], s1 = g_csr[i + 1];
        float sl0 = g_als2[s0];
        float sl1 = g_als2[s1];
        float h0 = g_h2[s0 * 32 + lane];
        float h1 = g_h2[s1 * 32 + lane];
        float w0 = __expf(leaky(sl0 + dld));
        float w1 = __expf(leaky(sl1 + dld));
        den += w0 + w1;
        acc += w0 * h0 + w1 * h1;
    }
    if (i < end) {
        int s = g_csr[i];
        float w = __expf(leaky(g_als2[s] + dld));
        den += w;
        acc += w * g_h2[s * 32 + lane];
    }
    out[node * 32 + lane] = acc / (den + 1e-16f) + b2[lane];
}

extern "C" void kernel_launch(void* const* d_in, const int* in_sizes, int n_in,
                              void* d_out, int out_size) {
    const float* x   = (const float*)d_in[0];
    const int*   ei  = (const int*)d_in[1];     // int64 inputs delivered as int32
    const float* W1  = (const float*)d_in[2];
    const float* as1 = (const float*)d_in[3];
    const float* ad1 = (const float*)d_in[4];
    const float* b1  = (const float*)d_in[5];
    const float* W2  = (const float*)d_in[6];
    const float* as2 = (const float*)d_in[7];
    const float* ad2 = (const float*)d_in[8];
    const float* b2  = (const float*)d_in[9];
    float* out = (float*)d_out;

    int n = in_sizes[0] / 128;   // 50000
    int e = in_sizes[1] / 2;     // 800000
    int nblk = (n + SCAN_BLK - 1) / SCAN_BLK;   // 196 <= 256
    int npair = (n + 1) / 2;

    // CSR build
    k_zero   <<<(n + 255) / 256, 256>>>(n);
    k_count  <<<(e + 255) / 256, 256>>>(ei, e);
    k_bsum   <<<nblk, SCAN_BLK>>>(n);
    k_bscan  <<<1, SCAN_BLK>>>(nblk);
    k_rowfill<<<nblk, SCAN_BLK>>>(n);
    k_fill   <<<(e + 255) / 256, 256>>>(ei, e);
    // layer 1
    k_gemm1<<<(npair + 7) / 8, 256>>>(n, x, W1, as1, ad1);
    k_agg1 <<<(n + 7) / 8, 256>>>(n, b1);
    // layer 2
    k_gemm2<<<(npair + 7) / 8, 256>>>(n, W2, as2, ad2);
    k_agg2 <<<(n + 7) / 8, 256>>>(n, b2, out);
}

// round 17
// speedup vs baseline: 1.3923x; 1.0584x over previous
#include <cuda_runtime.h>

// Fixed problem shape (from reference): N=50000, E=800000, IN=128, HID=32, HEADS=4
#define NMAX 50000
#define EMAX 800000
#define NEG_SLOPE 0.2f
#define SCAN_BLK 256

// -------- scratch (device globals: allocation-free, graph-capturable) --------
__device__ float g_h1 [NMAX * 128];    // layer1 raw features
__device__ float g_x2 [NMAX * 128];    // elu(layer1 out) = layer2 input
__device__ float g_als1[NMAX * 4];
__device__ float g_ald1[NMAX * 4];
__device__ float g_h2 [NMAX * 32];
__device__ float g_als2[NMAX];
__device__ float g_ald2[NMAX];
// CSR by destination
__device__ int g_cnt [NMAX];
__device__ int g_row [NMAX + 1];
__device__ int g_wpos[NMAX];
__device__ int g_csr [EMAX];
__device__ int g_bsum[512];

__device__ __forceinline__ float leaky(float v) {
    return v > 0.0f ? v : NEG_SLOPE * v;
}

// -------- CSR build --------
__global__ void k_zero(int n) {
    int i = blockIdx.x * blockDim.x + threadIdx.x;
    if (i < n) g_cnt[i] = 0;
}

__global__ void k_count(const int* __restrict__ ei, int e) {
    int t = blockIdx.x * blockDim.x + threadIdx.x;
    if (t < e) atomicAdd(&g_cnt[ei[e + t]], 1);   // dst
}

__global__ void k_bsum(int n) {
    __shared__ int sh[8];
    int i = blockIdx.x * SCAN_BLK + threadIdx.x;
    int c = (i < n) ? g_cnt[i] : 0;
#pragma unroll
    for (int o = 16; o > 0; o >>= 1) c += __shfl_xor_sync(0xffffffffu, c, o);
    if ((threadIdx.x & 31) == 0) sh[threadIdx.x >> 5] = c;
    __syncthreads();
    if (threadIdx.x == 0) {
        int v = 0;
#pragma unroll
        for (int w = 0; w < 8; w++) v += sh[w];
        g_bsum[blockIdx.x] = v;
    }
}

__global__ void k_bscan(int nblk) {
    __shared__ int sh[SCAN_BLK];
    int tid = threadIdx.x;
    int v = (tid < nblk) ? g_bsum[tid] : 0;
    sh[tid] = v;
    __syncthreads();
    for (int d = 1; d < SCAN_BLK; d <<= 1) {
        int t = (tid >= d) ? sh[tid - d] : 0;
        __syncthreads();
        sh[tid] += t;
        __syncthreads();
    }
    if (tid < nblk) g_bsum[tid] = sh[tid] - v;   // exclusive
}

__global__ void k_rowfill(int n) {
    __shared__ int sh[SCAN_BLK];
    int tid = threadIdx.x;
    int i = blockIdx.x * SCAN_BLK + tid;
    int c = (i < n) ? g_cnt[i] : 0;
    sh[tid] = c;
    __syncthreads();
    for (int d = 1; d < SCAN_BLK; d <<= 1) {
        int t = (tid >= d) ? sh[tid - d] : 0;
        __syncthreads();
        sh[tid] += t;
        __syncthreads();
    }
    int pref = g_bsum[blockIdx.x] + sh[tid] - c;   // exclusive prefix
    if (i < n) {
        g_row[i] = pref;
        g_wpos[i] = pref;
        if (i == n - 1) g_row[n] = pref + c;
    }
}

__global__ void k_fill(const int* __restrict__ ei, int e) {
    int t = blockIdx.x * blockDim.x + threadIdx.x;
    if (t >= e) return;
    int s = ei[t], d = ei[e + t];
    int pos = atomicAdd(&g_wpos[d], 1);
    g_csr[pos] = s;
}

// -------- layer1 GEMM (x @ W1) fused with logits; TWO nodes per warp --------
// lane owns output cols 4*lane..4*lane+3 (head = lane/8); W1 load amortized x2
__global__ void k_gemm1(int n, const float* __restrict__ x, const float* __restrict__ W1,
                        const float* __restrict__ as1, const float* __restrict__ ad1) {
    int gw   = (blockIdx.x * blockDim.x + threadIdx.x) >> 5;
    int lane = threadIdx.x & 31;
    int n0 = gw * 2;
    if (n0 >= n) return;
    bool has2 = (n0 + 1 < n);

    float xv0[4], xv1[4];
#pragma unroll
    for (int r = 0; r < 4; r++) {
        xv0[r] = x[n0 * 128 + lane + 32 * r];
        xv1[r] = has2 ? x[(n0 + 1) * 128 + lane + 32 * r] : 0.0f;
    }

    float b00 = 0.f, b01 = 0.f, b02 = 0.f, b03 = 0.f;
    float b10 = 0.f, b11 = 0.f, b12 = 0.f, b13 = 0.f;
#pragma unroll
    for (int k = 0; k < 128; k++) {
        float xk0 = __shfl_sync(0xffffffffu, xv0[k >> 5], k & 31);
        float xk1 = __shfl_sync(0xffffffffu, xv1[k >> 5], k & 31);
        float4 wv = *(const float4*)&W1[k * 128 + 4 * lane];   // L1-resident (64KB)
        b00 += xk0 * wv.x; b01 += xk0 * wv.y; b02 += xk0 * wv.z; b03 += xk0 * wv.w;
        b10 += xk1 * wv.x; b11 += xk1 * wv.y; b12 += xk1 * wv.z; b13 += xk1 * wv.w;
    }

    float4 sa = *(const float4*)&as1[4 * lane];
    float4 da = *(const float4*)&ad1[4 * lane];

    // node n0
    *(float4*)&g_h1[n0 * 128 + 4 * lane] = make_float4(b00, b01, b02, b03);
    float ps0 = b00 * sa.x + b01 * sa.y + b02 * sa.z + b03 * sa.w;
    float pd0 = b00 * da.x + b01 * da.y + b02 * da.z + b03 * da.w;
    float ps1 = b10 * sa.x + b11 * sa.y + b12 * sa.z + b13 * sa.w;
    float pd1 = b10 * da.x + b11 * da.y + b12 * da.z + b13 * da.w;
#pragma unroll
    for (int o = 1; o < 8; o <<= 1) {
        ps0 += __shfl_xor_sync(0xffffffffu, ps0, o);
        pd0 += __shfl_xor_sync(0xffffffffu, pd0, o);
        ps1 += __shfl_xor_sync(0xffffffffu, ps1, o);
        pd1 += __shfl_xor_sync(0xffffffffu, pd1, o);
    }
    if ((lane & 7) == 0) {
        int h = lane >> 3;
        g_als1[n0 * 4 + h] = ps0;
        g_ald1[n0 * 4 + h] = pd0;
    }
    if (has2) {
        *(float4*)&g_h1[(n0 + 1) * 128 + 4 * lane] = make_float4(b10, b11, b12, b13);
        if ((lane & 7) == 0) {
            int h = lane >> 3;
            g_als1[(n0 + 1) * 4 + h] = ps1;
            g_ald1[(n0 + 1) * 4 + h] = pd1;
        }
    }
}

// -------- layer1 aggregation: warp per dst node, single-pass (no segment max) --------
__global__ void k_agg1(int n, const float* __restrict__ b1) {
    int node = (blockIdx.x * blockDim.x + threadIdx.x) >> 5;
    int lane = threadIdx.x & 31;
    if (node >= n) return;
    int beg = g_row[node], end = g_row[node + 1];

    int head = lane >> 3;
    float dlh = g_ald1[node * 4 + head];

    float den = 0.f, a0 = 0.f, a1 = 0.f, a2 = 0.f, a3 = 0.f;
    { // self loop
        float slh = g_als1[node * 4 + head];
        float w = __expf(leaky(slh + dlh));
        den += w;
        float4 hv = *(const float4*)&g_h1[node * 128 + 4 * lane];
        a0 += w * hv.x; a1 += w * hv.y; a2 += w * hv.z; a3 += w * hv.w;
    }
#pragma unroll 2
    for (int i = beg; i < end; i++) {
        int s = g_csr[i];                        // uniform across warp
        float slh = g_als1[s * 4 + head];        // broadcast within head
        float w = __expf(leaky(slh + dlh));
        den += w;
        float4 hv = *(const float4*)&g_h1[s * 128 + 4 * lane];
        a0 += w * hv.x; a1 += w * hv.y; a2 += w * hv.z; a3 += w * hv.w;
    }
    float inv = 1.0f / (den + 1e-16f);
    float4 bb = *(const float4*)&b1[4 * lane];
    float v0 = a0 * inv + bb.x, v1 = a1 * inv + bb.y;
    float v2 = a2 * inv + bb.z, v3 = a3 * inv + bb.w;
    v0 = v0 > 0.f ? v0 : (__expf(v0) - 1.0f);
    v1 = v1 > 0.f ? v1 : (__expf(v1) - 1.0f);
    v2 = v2 > 0.f ? v2 : (__expf(v2) - 1.0f);
    v3 = v3 > 0.f ? v3 : (__expf(v3) - 1.0f);
    *(float4*)&g_x2[node * 128 + 4 * lane] = make_float4(v0, v1, v2, v3);
}

// -------- layer2 GEMM (x2 @ W2) fused with logits; TWO nodes per warp, lane = col --------
__global__ void k_gemm2(int n, const float* __restrict__ W2,
                        const float* __restrict__ as2, const float* __restrict__ ad2) {
    int gw   = (blockIdx.x * blockDim.x + threadIdx.x) >> 5;
    int lane = threadIdx.x & 31;
    int n0 = gw * 2;
    if (n0 >= n) return;
    bool has2 = (n0 + 1 < n);

    float xv0[4], xv1[4];
#pragma unroll
    for (int r = 0; r < 4; r++) {
        xv0[r] = g_x2[n0 * 128 + lane + 32 * r];
        xv1[r] = has2 ? g_x2[(n0 + 1) * 128 + lane + 32 * r] : 0.0f;
    }

    float acc0 = 0.0f, acc1 = 0.0f;
#pragma unroll
    for (int k = 0; k < 128; k++) {
        float xk0 = __shfl_sync(0xffffffffu, xv0[k >> 5], k & 31);
        float xk1 = __shfl_sync(0xffffffffu, xv1[k >> 5], k & 31);
        float wk = W2[k * 32 + lane];            // L1-resident (16KB)
        acc0 += xk0 * wk;
        acc1 += xk1 * wk;
    }
    g_h2[n0 * 32 + lane] = acc0;
    if (has2) g_h2[(n0 + 1) * 32 + lane] = acc1;

    float s2 = as2[lane], d2 = ad2[lane];
    float ps0 = acc0 * s2, pd0 = acc0 * d2;
    float ps1 = acc1 * s2, pd1 = acc1 * d2;
#pragma unroll
    for (int o = 16; o > 0; o >>= 1) {
        ps0 += __shfl_xor_sync(0xffffffffu, ps0, o);
        pd0 += __shfl_xor_sync(0xffffffffu, pd0, o);
        ps1 += __shfl_xor_sync(0xffffffffu, ps1, o);
        pd1 += __shfl_xor_sync(0xffffffffu, pd1, o);
    }
    if (lane == 0) {
        g_als2[n0] = ps0; g_ald2[n0] = pd0;
        if (has2) { g_als2[n0 + 1] = ps1; g_ald2[n0 + 1] = pd1; }
    }
}

// -------- layer2 aggregation: single-pass, warp per dst node, lane = col --------
__global__ void k_agg2(int n, const float* __restrict__ b2, float* __restrict__ out) {
    int node = (blockIdx.x * blockDim.x + threadIdx.x) >> 5;
    int lane = threadIdx.x & 31;
    if (node >= n) return;
    int beg = g_row[node], end = g_row[node + 1];

    float dld = g_ald2[node];

    float den = 0.f, acc = 0.f;
    { // self loop
        float w = __expf(leaky(g_als2[node] + dld));
        den += w;
        acc += w * g_h2[node * 32 + lane];
    }
#pragma unroll 2
    for (int i = beg; i < end; i++) {
        int s = g_csr[i];
        float w = __expf(leaky(g_als2[s] + dld));
        den += w;
        acc += w * g_h2[s * 32 + lane];
    }
    out[node * 32 + lane] = acc / (den + 1e-16f) + b2[lane];
}

extern "C" void kernel_launch(void* const* d_in, const int* in_sizes, int n_in,
                              void* d_out, int out_size) {
    const float* x   = (const float*)d_in[0];
    const int*   ei  = (const int*)d_in[1];     // int64 inputs delivered as int32
    const float* W1  = (const float*)d_in[2];
    const float* as1 = (const float*)d_in[3];
    const float* ad1 = (const float*)d_in[4];
    const float* b1  = (const float*)d_in[5];
    const float* W2  = (const float*)d_in[6];
    const float* as2 = (const float*)d_in[7];
    const float* ad2 = (const float*)d_in[8];
    const float* b2  = (const float*)d_in[9];
    float* out = (float*)d_out;

    int n = in_sizes[0] / 128;   // 50000
    int e = in_sizes[1] / 2;     // 800000
    int nblk = (n + SCAN_BLK - 1) / SCAN_BLK;   // 196 <= 256
    int npair = (n + 1) / 2;

    // side stream + events for a parallel graph branch (created once; host-side
    // objects only — no device memory). Same ops recorded every call.
    static cudaStream_t s_side = nullptr;
    static cudaEvent_t  s_fork = nullptr, s_join = nullptr;
    if (s_side == nullptr) {
        cudaStreamCreateWithFlags(&s_side, cudaStreamNonBlocking);
        cudaEventCreateWithFlags(&s_fork, cudaEventDisableTiming);
        cudaEventCreateWithFlags(&s_join, cudaEventDisableTiming);
    }

    // fork: gemm1 runs on the side branch, CSR build on the main branch
    cudaEventRecord(s_fork, 0);
    cudaStreamWaitEvent(s_side, s_fork, 0);
    k_gemm1<<<(npair + 7) / 8, 256, 0, s_side>>>(n, x, W1, as1, ad1);
    cudaEventRecord(s_join, s_side);

    // main branch: CSR build (independent of gemm1)
    k_zero   <<<(n + 255) / 256, 256>>>(n);
    k_count  <<<(e + 255) / 256, 256>>>(ei, e);
    k_bsum   <<<nblk, SCAN_BLK>>>(n);
    k_bscan  <<<1, SCAN_BLK>>>(nblk);
    k_rowfill<<<nblk, SCAN_BLK>>>(n);
    k_fill   <<<(e + 255) / 256, 256>>>(ei, e);

    // join: agg1 needs both CSR and gemm1 results
    cudaStreamWaitEvent(0, s_join, 0);
    k_agg1 <<<(n + 7) / 8, 256>>>(n, b1);
    // layer 2
    k_gemm2<<<(npair + 7) / 8, 256>>>(n, W2, as2, ad2);
    k_agg2 <<<(n + 7) / 8, 256>>>(n, b2, out);
}